// round 6
// baseline (speedup 1.0000x reference)
#include <cuda_runtime.h>

// SPDUnVectorize: x[B, L] packed upper triangle (row-major, incl. diag) ->
// out[B, n, n] symmetric. B=1024, n=256, L=n(n+1)/2=32896.
//
// One block = one upper-triangle 32x32 tile for FOUR consecutive batches.
// Single __syncthreads(); 16 coalesced loads in flight per thread before it.

#define NMAT   256
#define L_IN   32896
#define BATCH  1024
#define TILE   32
#define NTROW  8
#define NTILES 36
#define PAD    33
#define NB     4            // batches per block

__device__ __forceinline__ int tri_off(int r) {
    return r * NMAT - (r * (r - 1)) / 2;
}

__global__ __launch_bounds__(256, 6)
void spd_unvec_kernel(const float* __restrict__ in, float* __restrict__ out) {
    __shared__ float s[NB][TILE][PAD];

    const int b0 = blockIdx.y * NB;
    int t = blockIdx.x;

    int ti = 0;
    int rem = NTROW;
    while (t >= rem) { t -= rem; rem--; ti++; }
    const int tj = ti + t;

    const int lane = threadIdx.x & 31;   // column within tile
    const int wy   = threadIdx.x >> 5;   // 0..7 (base row)

    const float* __restrict__ inb  = in  + (size_t)b0 * L_IN;
    float*       __restrict__ outb = out + (size_t)b0 * (NMAT * NMAT);

    if (ti == tj) {
        // ---- Diagonal tile, NB batches ----
        #pragma unroll
        for (int k = 0; k < 4; k++) {
            const int lr = wy + k * 8;
            const int r  = ti * TILE + lr;
            if (lane >= lr) {
                const int idx = tri_off(r) + lane - lr;
                #pragma unroll
                for (int q = 0; q < NB; q++)
                    s[q][lr][lane] = inb[(size_t)q * L_IN + idx];
            }
        }
        __syncthreads();
        const int row = threadIdx.x >> 3;
        const int qc  = (threadIdx.x & 7) << 2;
        const int r   = ti * TILE + row;
        #pragma unroll
        for (int q = 0; q < NB; q++) {
            float4 v;
            #pragma unroll
            for (int k = 0; k < 4; k++) {
                const int c = qc + k;
                ((float*)&v)[k] = (c >= row) ? s[q][row][c] : s[q][c][row];
            }
            *reinterpret_cast<float4*>(
                &outb[(size_t)q * NMAT * NMAT + r * NMAT + ti * TILE + qc]) = v;
        }
    } else {
        // ---- Off-diagonal tile (ti < tj), NB batches ----
        // Warp = one row of 32 consecutive packed floats: fully coalesced.
        #pragma unroll
        for (int k = 0; k < 4; k++) {
            const int lr  = wy + k * 8;
            const int r   = ti * TILE + lr;
            const int idx = tri_off(r) - r + tj * TILE + lane;
            #pragma unroll
            for (int q = 0; q < NB; q++)
                s[q][lr][lane] = inb[(size_t)q * L_IN + idx];
        }
        __syncthreads();

        const int row = threadIdx.x >> 3;
        const int qc  = (threadIdx.x & 7) << 2;
        const int r   = ti * TILE + row;    // upper-tile row
        const int r2  = tj * TILE + row;    // mirror-tile row

        #pragma unroll
        for (int q = 0; q < NB; q++) {
            float* ob = outb + (size_t)q * NMAT * NMAT;
            float4 u, m;
            #pragma unroll
            for (int k = 0; k < 4; k++) {
                const int c = qc + k;
                ((float*)&u)[k] = s[q][row][c];
                ((float*)&m)[k] = s[q][c][row];
            }
            *reinterpret_cast<float4*>(&ob[r  * NMAT + tj * TILE + qc]) = u;
            *reinterpret_cast<float4*>(&ob[r2 * NMAT + ti * TILE + qc]) = m;
        }
    }
}

extern "C" void kernel_launch(void* const* d_in, const int* in_sizes, int n_in,
                              void* d_out, int out_size) {
    const float* in = (const float*)d_in[0];
    float* out = (float*)d_out;
    dim3 grid(NTILES, BATCH / NB);
    dim3 block(256);
    spd_unvec_kernel<<<grid, block>>>(in, out);
}